// round 9
// baseline (speedup 1.0000x reference)
#include <cuda_runtime.h>
#include <cuda_fp16.h>
#include <cstdint>
#include <cstddef>

#define NNODE 8192
#define DFEAT 128
#define SEC   1048576  // 8192*128

// ---------------- scratch (allocation-free __device__ globals) ----------------
__device__ __align__(16) __half g_adj16[(size_t)NNODE * NNODE]; // adj*8192 fp16 (128 MB)
__device__ __align__(16) __half g_B16[(size_t)NNODE * DFEAT];   // (h@W) fp16 row-major (2 MB)
__device__ __align__(16) float  g_H[(size_t)NNODE * DFEAT];     // raw PReLU output fp32 (4 MB)
__device__ __align__(16) float  g_P[2][(size_t)SEC];            // split-K partials (8 MB)
__device__ __align__(16) float  g_part[128][256];               // per-block col sum/sumsq
__device__ __align__(16) float  g_bn[2][DFEAT];                 // BN scale / shift

// ---------------- baseline-PTX helpers (sm_80-era; safe on .target sm_103) --------
__device__ __forceinline__ uint32_t smem_u32(const void* p) {
    uint32_t a;
    asm("{ .reg .u64 t; cvta.to.shared.u64 t, %1; cvt.u32.u64 %0, t; }" : "=r"(a) : "l"(p));
    return a;
}
__device__ __forceinline__ void cp16(uint32_t saddr, const void* gaddr) {
    asm volatile("cp.async.cg.shared.global [%0], [%1], 16;" :: "r"(saddr), "l"(gaddr));
}
#define CP_COMMIT() asm volatile("cp.async.commit_group;" ::: "memory")
#define CP_WAIT1()  asm volatile("cp.async.wait_group 1;" ::: "memory")

__device__ __forceinline__ void ldsm4(uint32_t* r, uint32_t a) {
    asm volatile("ldmatrix.sync.aligned.m8n8.x4.shared.b16 {%0,%1,%2,%3}, [%4];"
                 : "=r"(r[0]), "=r"(r[1]), "=r"(r[2]), "=r"(r[3]) : "r"(a));
}
__device__ __forceinline__ void ldsm4t(uint32_t* r, uint32_t a) {
    asm volatile("ldmatrix.sync.aligned.m8n8.x4.trans.shared.b16 {%0,%1,%2,%3}, [%4];"
                 : "=r"(r[0]), "=r"(r[1]), "=r"(r[2]), "=r"(r[3]) : "r"(a));
}
__device__ __forceinline__ void mma16816(float* c, const uint32_t* a, uint32_t b0, uint32_t b1) {
    asm volatile(
        "mma.sync.aligned.m16n8k16.row.col.f32.f16.f16.f32 "
        "{%0,%1,%2,%3}, {%4,%5,%6,%7}, {%8,%9}, {%0,%1,%2,%3};"
        : "+f"(c[0]), "+f"(c[1]), "+f"(c[2]), "+f"(c[3])
        : "r"(a[0]), "r"(a[1]), "r"(a[2]), "r"(a[3]), "r"(b0), "r"(b1));
}

#define SWA(o) ((o) ^ (((o) >> 3) & 0x70))   // swizzle for 128B rows
#define SWB(o) ((o) ^ (((o) >> 4) & 0xF0))   // swizzle for 256B rows

// packed fp32x2 FMA helpers (bitwise-identical per-scalar chains)
__device__ __forceinline__ void fma2(uint64_t& d, uint64_t a, uint64_t b) {
    asm("fma.rn.f32x2 %0, %1, %2, %3;" : "=l"(d) : "l"(a), "l"(b), "l"(d));
}
__device__ __forceinline__ uint64_t dup2(float x) {
    uint64_t r; asm("mov.b64 %0, {%1, %1};" : "=l"(r) : "f"(x)); return r;
}
__device__ __forceinline__ float2 unp2(uint64_t v) {
    float2 r; asm("mov.b64 {%0, %1}, %2;" : "=f"(r.x), "=f"(r.y) : "l"(v)); return r;
}

// ---------------- kernels ----------------

// adj fp32 -> fp16 * 8192
__global__ void __launch_bounds__(256) k_convert(const float* __restrict__ adj) {
    size_t i = ((size_t)blockIdx.x * 256 + threadIdx.x) * 8;
    float4 a = *(const float4*)(adj + i);
    float4 b = *(const float4*)(adj + i + 4);
    __half2 h0 = __floats2half2_rn(a.x * 8192.f, a.y * 8192.f);
    __half2 h1 = __floats2half2_rn(a.z * 8192.f, a.w * 8192.f);
    __half2 h2 = __floats2half2_rn(b.x * 8192.f, b.y * 8192.f);
    __half2 h3 = __floats2half2_rn(b.z * 8192.f, b.w * 8192.f);
    uint4 o;
    o.x = *(uint32_t*)&h0; o.y = *(uint32_t*)&h1;
    o.z = *(uint32_t*)&h2; o.w = *(uint32_t*)&h3;
    *(uint4*)(&g_adj16[i]) = o;
}

// x_m -> out sec0 + g_H ; mask -> out sec3
__global__ void __launch_bounds__(256) k_mask(const float* __restrict__ x,
                                              const float* __restrict__ mask,
                                              const float* __restrict__ noise,
                                              float* __restrict__ out) {
    size_t g = ((size_t)blockIdx.x * 256 + threadIdx.x) * 4;
    float4 xv = *(const float4*)(x + g);
    float4 mv = *(const float4*)(mask + g);
    float4 nv = *(const float4*)(noise + g);
    float4 v;
    v.x = xv.x * (1.f - mv.x) + nv.x * mv.x;
    v.y = xv.y * (1.f - mv.y) + nv.y * mv.y;
    v.z = xv.z * (1.f - mv.z) + nv.z * mv.z;
    v.w = xv.w * (1.f - mv.w) + nv.w * mv.w;
    *(float4*)(out + g) = v;
    *(float4*)(out + 3 * (size_t)SEC + g) = mv;
    *(float4*)(g_H + g) = v;
}

// Deterministic BN stats: one block per column; 128 threads each load one per-block
// partial, fixed-order smem tree reduce, write scale/shift to g_bn.
__global__ void __launch_bounds__(128) k_stats(const float* __restrict__ gamma,
                                               const float* __restrict__ beta) {
    __shared__ float sm_s[128], sm_q[128];
    int c = blockIdx.x, tid = threadIdx.x;
    sm_s[tid] = g_part[tid][c];
    sm_q[tid] = g_part[tid][128 + c];
    __syncthreads();
#pragma unroll
    for (int d = 64; d > 0; d >>= 1) {
        if (tid < d) { sm_s[tid] += sm_s[tid + d]; sm_q[tid] += sm_q[tid + d]; }
        __syncthreads();
    }
    if (tid == 0) {
        const float inN = 1.f / 8192.f;
        float mu = sm_s[0] * inN;
        float var = sm_q[0] * inN - mu * mu;
        float a = gamma[c] * rsqrtf(var + 1e-5f);
        g_bn[0][c] = a;
        g_bn[1][c] = beta[c] - a * mu;
    }
}

// HW = BN(g_H) @ W in exact fp32 (affine from g_bn applied inline while loading H);
// quantize to fp16 row-major g_B16. Optionally writes normalized H to wout.
__global__ void __launch_bounds__(256) k_hw(const float* __restrict__ W,
                                            int use_stats,
                                            float* __restrict__ wout) {
    extern __shared__ float sm_hw[];
    float* Hs = sm_hw;              // [32][129]
    float* Ws = sm_hw + 32 * 129;   // [128][128]
    __shared__ float sa[128], st[128];
    int tid = threadIdx.x;
    int r0 = blockIdx.x * 32;

    if (tid < 128) {
        if (use_stats) { sa[tid] = g_bn[0][tid]; st[tid] = g_bn[1][tid]; }
        else           { sa[tid] = 1.f;          st[tid] = 0.f; }
    }
    __syncthreads();

#pragma unroll
    for (int j = 0; j < 4; j++) {             // H tile 32x128, BN affine inline
        int v = tid + j * 256;
        int row = v >> 5, c4 = (v & 31) * 4;
        float4 f = *(const float4*)(g_H + (size_t)(r0 + row) * 128 + c4);
        float4 nv;
        nv.x = f.x * sa[c4 + 0] + st[c4 + 0];
        nv.y = f.y * sa[c4 + 1] + st[c4 + 1];
        nv.z = f.z * sa[c4 + 2] + st[c4 + 2];
        nv.w = f.w * sa[c4 + 3] + st[c4 + 3];
        float* d = Hs + row * 129 + c4;
        d[0] = nv.x; d[1] = nv.y; d[2] = nv.z; d[3] = nv.w;
        if (wout) *(float4*)(wout + (size_t)(r0 + row) * 128 + c4) = nv;
    }
#pragma unroll
    for (int j = 0; j < 16; j++)              // W 128x128
        ((float4*)Ws)[tid + j * 256] = ((const float4*)W)[tid + j * 256];
    __syncthreads();

    int l = tid & 31, w = tid >> 5, cw = w * 16;
    uint64_t acc2[8];
#pragma unroll
    for (int j = 0; j < 8; j++) acc2[j] = 0ull;

#pragma unroll 4
    for (int k = 0; k < 128; k++) {
        uint64_t a0 = dup2(Hs[l * 129 + k]);
        const uint64_t* wr = (const uint64_t*)(Ws + k * 128 + cw);
#pragma unroll
        for (int q = 0; q < 8; q++) fma2(acc2[q], a0, wr[q]);
    }
    int rA = r0 + l;
#pragma unroll
    for (int j = 0; j < 8; j++) {
        float2 va = unp2(acc2[j]);
        *(__half2*)&g_B16[(size_t)rA * 128 + cw + 2 * j] = __floats2half2_rn(va.x, va.y);
    }
}

// Big GEMM (split-K): raw partial P_kh = adj16[:, kh] @ B16[kh, :] -> g_P[kh].
// 512 CTAs = 128 m-tiles x 2 n-halves x 2 k-halves; CTA tile M=64 N=64,
// 128 threads (2x2 warps m32n32), Kc=128/stage, 3-stage cp.async pipeline,
// fragment double-buffer. No epilogue (k_comb applies it).
__global__ void __launch_bounds__(128) k_big() {
    extern __shared__ char smem[];
    uint32_t sb = smem_u32(smem);
    const int tid = threadIdx.x, w = tid >> 5, l = tid & 31;
    const int bx = blockIdx.x;
    const int m0 = (bx >> 2) * 64;
    const int n0 = ((bx >> 1) & 1) * 64;
    const int kh = bx & 1;
    const int wm = w >> 1, wn = w & 1;      // 2x2 warp grid, m32n32 each
    const int STAGE = 32768;                // A 16KB (64x256B) + B 16KB (128x128B)

    // ---- cp.async source pointers + precomputed swizzled dst offsets ----
    const int arow0 = tid >> 4, au = tid & 15;
    const __half* pA = g_adj16 + (size_t)(m0 + arow0) * NNODE + kh * 4096 + au * 8;
    uint32_t dAo[8];
#pragma unroll
    for (int i = 0; i < 8; i++)
        dAo[i] = SWB((uint32_t)((arow0 + 8 * i) * 256 + au * 16));
    const int brow0 = tid >> 3, bu = tid & 7;
    const __half* pB = g_B16 + (size_t)(kh * 4096 + brow0) * 128 + n0 + bu * 8;
    uint32_t dBo[8];
#pragma unroll
    for (int i = 0; i < 8; i++)
        dBo[i] = 16384u + SWA((uint32_t)((brow0 + 16 * i) * 128 + bu * 16));

    auto load_stage = [&](uint32_t as) {
#pragma unroll
        for (int i = 0; i < 8; i++) {
            cp16(as + dAo[i], pA + (size_t)(8 * i) * NNODE);
            cp16(as + dBo[i], pB + 16 * i * 128);
        }
        pA += 128;          // next K chunk (128 cols)
        pB += 128 * 128;    // next 128 K-rows
    };

    // ---- ldsm offsets ----
    uint32_t aoff[2][8];
#pragma unroll
    for (int kk = 0; kk < 8; kk++)
#pragma unroll
        for (int ti = 0; ti < 2; ti++) {
            int mrow = wm * 32 + ti * 16 + (l & 15);
            int kcol = kk * 16 + (l >> 4) * 8;
            aoff[ti][kk] = SWB((uint32_t)(mrow * 256 + kcol * 2));
        }
    uint32_t boff[2];
#pragma unroll
    for (int tj = 0; tj < 2; tj++) {
        int krow = l & 15;
        int ncol = wn * 32 + tj * 16 + (l >> 4) * 8;
        boff[tj] = 16384u + SWA((uint32_t)(krow * 128 + ncol * 2));
    }

    float acc[2][4][4];
#pragma unroll
    for (int i = 0; i < 2; i++)
#pragma unroll
        for (int j = 0; j < 4; j++)
#pragma unroll
            for (int q = 0; q < 4; q++) acc[i][j][q] = 0.f;

    uint32_t afr[2][2][4], bfr[2][2][4];

    load_stage(sb);             CP_COMMIT();
    load_stage(sb + STAGE);     CP_COMMIT();

    uint32_t as_c = sb;                 // stage being computed (t)
    uint32_t as_l = sb + 2 * STAGE;     // stage being loaded (t+2)

    for (int t = 0; t < 32; ++t) {
        CP_WAIT1();
        __syncthreads();
        if (t + 2 < 32) load_stage(as_l);
        CP_COMMIT();

        ldsm4 (afr[0][0], as_c + aoff[0][0]);
        ldsm4 (afr[0][1], as_c + aoff[1][0]);
        ldsm4t(bfr[0][0], as_c + boff[0]);
        ldsm4t(bfr[0][1], as_c + boff[1]);
#pragma unroll
        for (int kk = 0; kk < 8; kk++) {
            int fb = kk & 1;
            if (kk < 7) {
                uint32_t bk = (uint32_t)(kk + 1) * 2048u;
                ldsm4 (afr[fb ^ 1][0], as_c + aoff[0][kk + 1]);
                ldsm4 (afr[fb ^ 1][1], as_c + aoff[1][kk + 1]);
                ldsm4t(bfr[fb ^ 1][0], as_c + boff[0] + bk);
                ldsm4t(bfr[fb ^ 1][1], as_c + boff[1] + bk);
            }
#pragma unroll
            for (int ti = 0; ti < 2; ti++)
#pragma unroll
                for (int tj = 0; tj < 4; tj++)
                    mma16816(acc[ti][tj], afr[fb][ti],
                             bfr[fb][tj >> 1][2 * (tj & 1)],
                             bfr[fb][tj >> 1][2 * (tj & 1) + 1]);
        }
        __syncthreads();
        as_c += STAGE; if (as_c == sb + 3 * STAGE) as_c = sb;
        as_l += STAGE; if (as_l == sb + 3 * STAGE) as_l = sb;
    }

    // store raw partials
    float* gp = g_P[kh];
#pragma unroll
    for (int ti = 0; ti < 2; ti++) {
        int row = m0 + wm * 32 + ti * 16 + (l >> 2);
#pragma unroll
        for (int tj = 0; tj < 4; tj++) {
            int col = n0 + wn * 32 + tj * 8 + (l & 3) * 2;
            *(float2*)(gp + (size_t)row * 128 + col)       = make_float2(acc[ti][tj][0], acc[ti][tj][1]);
            *(float2*)(gp + (size_t)(row + 8) * 128 + col) = make_float2(acc[ti][tj][2], acc[ti][tj][3]);
        }
    }
}

// Combine split-K partials: z = prelu((P0+P1)/8192 + bias) -> g_H or outp.
// 128 blocks x 64 rows, 256 threads; deterministic per-block column stats -> g_part.
__global__ void __launch_bounds__(256) k_comb(const float* __restrict__ bias,
                                              const float* __restrict__ alpha,
                                              float* __restrict__ outp, int to_out,
                                              int do_stats) {
    __shared__ float ssum[8][128], ssq[8][128];
    int bx = blockIdx.x, tid = threadIdx.x;
    int rg = tid >> 5;                    // row group 0..7
    int c4 = (tid & 31) * 4;
    int r0 = bx * 64 + rg * 8;
    float al = alpha[0];
    const float s = 1.f / 8192.f;
    float4 bb = *(const float4*)(bias + c4);
    float* dst = to_out ? outp : g_H;
    float sum0 = 0, sum1 = 0, sum2 = 0, sum3 = 0;
    float sq0 = 0, sq1 = 0, sq2 = 0, sq3 = 0;
#pragma unroll
    for (int r = 0; r < 8; r++) {
        size_t idx = (size_t)(r0 + r) * 128 + c4;
        float4 p0 = *(const float4*)(g_P[0] + idx);
        float4 p1 = *(const float4*)(g_P[1] + idx);
        float4 v;
        v.x = (p0.x + p1.x) * s + bb.x;
        v.y = (p0.y + p1.y) * s + bb.y;
        v.z = (p0.z + p1.z) * s + bb.z;
        v.w = (p0.w + p1.w) * s + bb.w;
        v.x = v.x >= 0.f ? v.x : al * v.x;
        v.y = v.y >= 0.f ? v.y : al * v.y;
        v.z = v.z >= 0.f ? v.z : al * v.z;
        v.w = v.w >= 0.f ? v.w : al * v.w;
        *(float4*)(dst + idx) = v;
        sum0 += v.x; sq0 += v.x * v.x;
        sum1 += v.y; sq1 += v.y * v.y;
        sum2 += v.z; sq2 += v.z * v.z;
        sum3 += v.w; sq3 += v.w * v.w;
    }
    if (do_stats) {
        ssum[rg][c4 + 0] = sum0; ssq[rg][c4 + 0] = sq0;
        ssum[rg][c4 + 1] = sum1; ssq[rg][c4 + 1] = sq1;
        ssum[rg][c4 + 2] = sum2; ssq[rg][c4 + 2] = sq2;
        ssum[rg][c4 + 3] = sum3; ssq[rg][c4 + 3] = sq3;
        __syncthreads();
        if (tid < 128) {
            float S = 0.f, Q = 0.f;
#pragma unroll
            for (int g = 0; g < 8; g++) { S += ssum[g][tid]; Q += ssq[g][tid]; }
            g_part[bx][tid] = S;
            g_part[bx][128 + tid] = Q;
        }
    }
}

// ---------------- launch ----------------
extern "C" void kernel_launch(void* const* d_in, const int* in_sizes, int n_in,
                              void* d_out, int out_size) {
    const float* x     = (const float*)d_in[0];
    const float* adj   = (const float*)d_in[1];
    const float* mask  = (const float*)d_in[2];
    const float* noise = (const float*)d_in[3];
    const float* eW = (const float*)d_in[4];
    const float* eb = (const float*)d_in[5];
    const float* ea = (const float*)d_in[6];
    const float* eg = (const float*)d_in[7];
    const float* eB = (const float*)d_in[8];
    const float* dW = (const float*)d_in[9];
    const float* db = (const float*)d_in[10];
    const float* da = (const float*)d_in[11];
    const float* dg = (const float*)d_in[12];
    const float* dB = (const float*)d_in[13];
    float* out = (float*)d_out;

    const int SMEM_BIG = 3 * 32768;                   // 98304
    const int SMEM_HW  = (32 * 129 + 128 * 128) * 4;  // 82048
    cudaFuncSetAttribute(k_big, cudaFuncAttributeMaxDynamicSharedMemorySize, SMEM_BIG);
    cudaFuncSetAttribute(k_hw,  cudaFuncAttributeMaxDynamicSharedMemorySize, SMEM_HW);

    k_convert<<<32768, 256>>>(adj);
    k_mask<<<1024, 256>>>(x, mask, noise, out);

    // 10 layers: j=0..4 encoder, j=5..9 decoder.
    // k_stats(j): BN params of layer j-1 -> g_bn.  k_hw(j): BN inline + @W_j -> g_B16.
    // k_big(j): split-K partials.  k_comb(j): combine + bias + prelu -> g_H/out + stats.
    for (int j = 0; j < 10; j++) {
        const float *W, *bi, *al;
        if (j < 5) { W = eW + (size_t)j * 16384; bi = eb + j * 128; al = ea + j; }
        else { int i = j - 5; W = dW + (size_t)i * 16384; bi = db + i * 128; al = da + i; }

        if (j >= 1) {
            const float *g, *bt;
            if (j <= 5) { g = eg + (j - 1) * 128; bt = eB + (j - 1) * 128; }
            else        { g = dg + (j - 6) * 128; bt = dB + (j - 6) * 128; }
            k_stats<<<128, 128>>>(g, bt);
        }

        float* wout = (j == 5) ? out + (size_t)SEC : nullptr;  // encoded = BN(enc5 out)
        k_hw<<<256, 256, SMEM_HW>>>(W, j > 0 ? 1 : 0, wout);

        k_big<<<512, 128, SMEM_BIG>>>();
        float* dst = (j == 9) ? out + 2 * (size_t)SEC : nullptr;
        k_comb<<<128, 256>>>(bi, al, dst, j == 9 ? 1 : 0, j < 9 ? 1 : 0);
    }
}

// round 10
// speedup vs baseline: 1.0564x; 1.0564x over previous
#include <cuda_runtime.h>
#include <cuda_fp16.h>
#include <cstdint>
#include <cstddef>

#define NNODE 8192
#define DFEAT 128
#define SEC   1048576  // 8192*128

// ---------------- scratch (allocation-free __device__ globals) ----------------
__device__ __align__(16) __half g_adj16[(size_t)NNODE * NNODE]; // adj*8192 fp16 (128 MB)
__device__ __align__(16) __half g_B16[(size_t)NNODE * DFEAT];   // (h@W) fp16 row-major (2 MB)
__device__ __align__(16) float  g_H[(size_t)NNODE * DFEAT];     // raw PReLU output fp32 (4 MB)
__device__ __align__(16) float  g_part[256][128];               // per-CTA col partials
__device__ __align__(16) float  g_bn[2][DFEAT];                 // BN scale / shift

// ---------------- baseline-PTX helpers (sm_80-era; safe on .target sm_103) --------
__device__ __forceinline__ uint32_t smem_u32(const void* p) {
    uint32_t a;
    asm("{ .reg .u64 t; cvta.to.shared.u64 t, %1; cvt.u32.u64 %0, t; }" : "=r"(a) : "l"(p));
    return a;
}
__device__ __forceinline__ void cp16(uint32_t saddr, const void* gaddr) {
    asm volatile("cp.async.cg.shared.global [%0], [%1], 16;" :: "r"(saddr), "l"(gaddr));
}
#define CP_COMMIT() asm volatile("cp.async.commit_group;" ::: "memory")
#define CP_WAIT2()  asm volatile("cp.async.wait_group 2;" ::: "memory")

__device__ __forceinline__ void ldsm4(uint32_t* r, uint32_t a) {
    asm volatile("ldmatrix.sync.aligned.m8n8.x4.shared.b16 {%0,%1,%2,%3}, [%4];"
                 : "=r"(r[0]), "=r"(r[1]), "=r"(r[2]), "=r"(r[3]) : "r"(a));
}
__device__ __forceinline__ void ldsm4t(uint32_t* r, uint32_t a) {
    asm volatile("ldmatrix.sync.aligned.m8n8.x4.trans.shared.b16 {%0,%1,%2,%3}, [%4];"
                 : "=r"(r[0]), "=r"(r[1]), "=r"(r[2]), "=r"(r[3]) : "r"(a));
}
__device__ __forceinline__ void mma16816(float* c, const uint32_t* a, uint32_t b0, uint32_t b1) {
    asm volatile(
        "mma.sync.aligned.m16n8k16.row.col.f32.f16.f16.f32 "
        "{%0,%1,%2,%3}, {%4,%5,%6,%7}, {%8,%9}, {%0,%1,%2,%3};"
        : "+f"(c[0]), "+f"(c[1]), "+f"(c[2]), "+f"(c[3])
        : "r"(a[0]), "r"(a[1]), "r"(a[2]), "r"(a[3]), "r"(b0), "r"(b1));
}

#define SWA(o) ((o) ^ (((o) >> 3) & 0x70))   // swizzle for 128B rows
#define SWB(o) ((o) ^ (((o) >> 4) & 0xF0))   // swizzle for 256B rows

// packed fp32x2 FMA helpers (bitwise-identical per-scalar chains)
__device__ __forceinline__ void fma2(uint64_t& d, uint64_t a, uint64_t b) {
    asm("fma.rn.f32x2 %0, %1, %2, %3;" : "=l"(d) : "l"(a), "l"(b), "l"(d));
}
__device__ __forceinline__ uint64_t dup2(float x) {
    uint64_t r; asm("mov.b64 %0, {%1, %1};" : "=l"(r) : "f"(x)); return r;
}
__device__ __forceinline__ float2 unp2(uint64_t v) {
    float2 r; asm("mov.b64 {%0, %1}, %2;" : "=f"(r.x), "=f"(r.y) : "l"(v)); return r;
}

// ---------------- kernels ----------------

// adj fp32 -> fp16 * 8192
__global__ void __launch_bounds__(256) k_convert(const float* __restrict__ adj) {
    size_t i = ((size_t)blockIdx.x * 256 + threadIdx.x) * 8;
    float4 a = *(const float4*)(adj + i);
    float4 b = *(const float4*)(adj + i + 4);
    __half2 h0 = __floats2half2_rn(a.x * 8192.f, a.y * 8192.f);
    __half2 h1 = __floats2half2_rn(a.z * 8192.f, a.w * 8192.f);
    __half2 h2 = __floats2half2_rn(b.x * 8192.f, b.y * 8192.f);
    __half2 h3 = __floats2half2_rn(b.z * 8192.f, b.w * 8192.f);
    uint4 o;
    o.x = *(uint32_t*)&h0; o.y = *(uint32_t*)&h1;
    o.z = *(uint32_t*)&h2; o.w = *(uint32_t*)&h3;
    *(uint4*)(&g_adj16[i]) = o;
}

// x_m -> out sec0 + g_H ; mask -> out sec3
__global__ void __launch_bounds__(256) k_mask(const float* __restrict__ x,
                                              const float* __restrict__ mask,
                                              const float* __restrict__ noise,
                                              float* __restrict__ out) {
    size_t g = ((size_t)blockIdx.x * 256 + threadIdx.x) * 4;
    float4 xv = *(const float4*)(x + g);
    float4 mv = *(const float4*)(mask + g);
    float4 nv = *(const float4*)(noise + g);
    float4 v;
    v.x = xv.x * (1.f - mv.x) + nv.x * mv.x;
    v.y = xv.y * (1.f - mv.y) + nv.y * mv.y;
    v.z = xv.z * (1.f - mv.z) + nv.z * mv.z;
    v.w = xv.w * (1.f - mv.w) + nv.w * mv.w;
    *(float4*)(out + g) = v;
    *(float4*)(out + 3 * (size_t)SEC + g) = mv;
    *(float4*)(g_H + g) = v;
}

// Deterministic BN stats: one block per column; 128 threads each load one per-CTA
// partial, fixed-order smem tree reduce, write scale/shift to g_bn.
__global__ void __launch_bounds__(128) k_stats(const float* __restrict__ gamma,
                                               const float* __restrict__ beta) {
    __shared__ float sm_s[128], sm_q[128];
    int c = blockIdx.x, tid = threadIdx.x;
    int half = c >> 6, lc = c & 63;
    sm_s[tid] = g_part[2 * tid + half][lc];
    sm_q[tid] = g_part[2 * tid + half][64 + lc];
    __syncthreads();
#pragma unroll
    for (int d = 64; d > 0; d >>= 1) {
        if (tid < d) { sm_s[tid] += sm_s[tid + d]; sm_q[tid] += sm_q[tid + d]; }
        __syncthreads();
    }
    if (tid == 0) {
        const float inN = 1.f / 8192.f;
        float mu = sm_s[0] * inN;
        float var = sm_q[0] * inN - mu * mu;
        float a = gamma[c] * rsqrtf(var + 1e-5f);
        g_bn[0][c] = a;
        g_bn[1][c] = beta[c] - a * mu;
    }
}

// HW = BN(g_H) @ W in exact fp32 (affine from g_bn inline while loading H);
// quantize to fp16 row-major g_B16. Optionally writes normalized H to wout.
// 128 blocks x 64 rows, 256 threads: warp w -> cols w*16..+15, lane l -> rows l, l+32.
// W smem loads amortized over 2 rows (halves LDS pressure vs 1 row/thread).
__global__ void __launch_bounds__(256) k_hw(const float* __restrict__ W,
                                            int use_stats,
                                            float* __restrict__ wout) {
    extern __shared__ float sm_hw[];
    float* Hs = sm_hw;              // [64][129]
    float* Ws = sm_hw + 64 * 129;   // [128][128]
    __shared__ float sa[128], st[128];
    int tid = threadIdx.x;
    int r0 = blockIdx.x * 64;

    if (tid < 128) {
        if (use_stats) { sa[tid] = g_bn[0][tid]; st[tid] = g_bn[1][tid]; }
        else           { sa[tid] = 1.f;          st[tid] = 0.f; }
    }
    __syncthreads();

#pragma unroll
    for (int j = 0; j < 8; j++) {             // H tile 64x128, BN affine inline
        int v = tid + j * 256;
        int row = v >> 5, c4 = (v & 31) * 4;
        float4 f = *(const float4*)(g_H + (size_t)(r0 + row) * 128 + c4);
        float4 nv;
        nv.x = f.x * sa[c4 + 0] + st[c4 + 0];
        nv.y = f.y * sa[c4 + 1] + st[c4 + 1];
        nv.z = f.z * sa[c4 + 2] + st[c4 + 2];
        nv.w = f.w * sa[c4 + 3] + st[c4 + 3];
        float* d = Hs + row * 129 + c4;
        d[0] = nv.x; d[1] = nv.y; d[2] = nv.z; d[3] = nv.w;
        if (wout) *(float4*)(wout + (size_t)(r0 + row) * 128 + c4) = nv;
    }
#pragma unroll
    for (int j = 0; j < 16; j++)              // W 128x128
        ((float4*)Ws)[tid + j * 256] = ((const float4*)W)[tid + j * 256];
    __syncthreads();

    int l = tid & 31, w = tid >> 5, cw = w * 16;
    uint64_t accA[8], accB[8];
#pragma unroll
    for (int j = 0; j < 8; j++) { accA[j] = 0ull; accB[j] = 0ull; }

#pragma unroll 4
    for (int k = 0; k < 128; k++) {
        uint64_t a0 = dup2(Hs[l * 129 + k]);
        uint64_t a1 = dup2(Hs[(l + 32) * 129 + k]);
        const uint64_t* wr = (const uint64_t*)(Ws + k * 128 + cw);
#pragma unroll
        for (int q = 0; q < 8; q++) {
            uint64_t wv = wr[q];
            fma2(accA[q], a0, wv);
            fma2(accB[q], a1, wv);
        }
    }
    int rA = r0 + l, rB = rA + 32;
#pragma unroll
    for (int j = 0; j < 8; j++) {
        float2 va = unp2(accA[j]);
        float2 vb = unp2(accB[j]);
        *(__half2*)&g_B16[(size_t)rA * 128 + cw + 2 * j] = __floats2half2_rn(va.x, va.y);
        *(__half2*)&g_B16[(size_t)rB * 128 + cw + 2 * j] = __floats2half2_rn(vb.x, vb.y);
    }
}

// Big GEMM: P = adj16 @ B16 ; z = prelu(P/8192 + bias) -> g_H or outp.
// 256 CTAs = 128 m-tiles x 2 n-halves; CTA tile M=64 N=64, 128 threads (2x2 warps
// m32n32), 2 CTAs/SM. Kc=128/stage, 3-stage cp.async pipeline with loads issued
// BEFORE the wait (wait_group 2), fragment double-buffer across 8 k16-steps.
// Deterministic per-CTA stats -> g_part.
__global__ void __launch_bounds__(128) k_big(const float* __restrict__ bias,
                                             const float* __restrict__ alpha,
                                             float* __restrict__ outp, int to_out,
                                             int do_stats) {
    extern __shared__ char smem[];
    uint32_t sb = smem_u32(smem);
    const int tid = threadIdx.x, w = tid >> 5, l = tid & 31;
    const int bx = blockIdx.x;
    const int m0 = (bx >> 1) * 64;
    const int n0 = (bx & 1) * 64;
    const int wm = w >> 1, wn = w & 1;      // 2x2 warp grid, m32n32 each
    const int STAGE = 32768;                // A 16KB (64x256B) + B 16KB (128x128B)

    // ---- cp.async source pointers + precomputed swizzled dst offsets ----
    const int arow0 = tid >> 4, au = tid & 15;
    const __half* pA = g_adj16 + (size_t)(m0 + arow0) * NNODE + au * 8;
    uint32_t dAo[8];
#pragma unroll
    for (int i = 0; i < 8; i++)
        dAo[i] = SWB((uint32_t)((arow0 + 8 * i) * 256 + au * 16));
    const int brow0 = tid >> 3, bu = tid & 7;
    const __half* pB = g_B16 + (size_t)brow0 * 128 + n0 + bu * 8;
    uint32_t dBo[8];
#pragma unroll
    for (int i = 0; i < 8; i++)
        dBo[i] = 16384u + SWA((uint32_t)((brow0 + 16 * i) * 128 + bu * 16));

    auto load_stage = [&](uint32_t as) {
#pragma unroll
        for (int i = 0; i < 8; i++) {
            cp16(as + dAo[i], pA + (size_t)(8 * i) * NNODE);
            cp16(as + dBo[i], pB + 16 * i * 128);
        }
        pA += 128;          // next K chunk (128 cols)
        pB += 128 * 128;    // next 128 K-rows
    };

    // ---- ldsm offsets ----
    uint32_t aoff[2][8];
#pragma unroll
    for (int kk = 0; kk < 8; kk++)
#pragma unroll
        for (int ti = 0; ti < 2; ti++) {
            int mrow = wm * 32 + ti * 16 + (l & 15);
            int kcol = kk * 16 + (l >> 4) * 8;
            aoff[ti][kk] = SWB((uint32_t)(mrow * 256 + kcol * 2));
        }
    uint32_t boff[2];
#pragma unroll
    for (int tj = 0; tj < 2; tj++) {
        int krow = l & 15;
        int ncol = wn * 32 + tj * 16 + (l >> 4) * 8;
        boff[tj] = 16384u + SWA((uint32_t)(krow * 128 + ncol * 2));
    }

    float acc[2][4][4];
#pragma unroll
    for (int i = 0; i < 2; i++)
#pragma unroll
        for (int j = 0; j < 4; j++)
#pragma unroll
            for (int q = 0; q < 4; q++) acc[i][j][q] = 0.f;

    uint32_t afr[2][2][4], bfr[2][2][4];

    load_stage(sb);             CP_COMMIT();
    load_stage(sb + STAGE);     CP_COMMIT();

    uint32_t as_c = sb;                 // stage being computed (t)
    uint32_t as_l = sb + 2 * STAGE;     // stage being loaded (t+2)

    for (int t = 0; t < 64; ++t) {
        // Issue next-stage loads BEFORE waiting: slot (t+2)%3 == (t-1)%3, whose
        // readers finished before iter t-1's trailing barrier. Empty commits in
        // the tail keep the wait_group count consistent.
        if (t + 2 < 64) load_stage(as_l);
        CP_COMMIT();
        CP_WAIT2();                 // group t complete (t+1, t+2 still in flight)
        __syncthreads();

        ldsm4 (afr[0][0], as_c + aoff[0][0]);
        ldsm4 (afr[0][1], as_c + aoff[1][0]);
        ldsm4t(bfr[0][0], as_c + boff[0]);
        ldsm4t(bfr[0][1], as_c + boff[1]);
#pragma unroll
        for (int kk = 0; kk < 8; kk++) {
            int fb = kk & 1;
            if (kk < 7) {
                uint32_t bk = (uint32_t)(kk + 1) * 2048u;
                ldsm4 (afr[fb ^ 1][0], as_c + aoff[0][kk + 1]);
                ldsm4 (afr[fb ^ 1][1], as_c + aoff[1][kk + 1]);
                ldsm4t(bfr[fb ^ 1][0], as_c + boff[0] + bk);
                ldsm4t(bfr[fb ^ 1][1], as_c + boff[1] + bk);
            }
#pragma unroll
            for (int ti = 0; ti < 2; ti++)
#pragma unroll
                for (int tj = 0; tj < 4; tj++)
                    mma16816(acc[ti][tj], afr[fb][ti],
                             bfr[fb][tj >> 1][2 * (tj & 1)],
                             bfr[fb][tj >> 1][2 * (tj & 1) + 1]);
        }
        __syncthreads();
        as_c += STAGE; if (as_c == sb + 3 * STAGE) as_c = sb;
        as_l += STAGE; if (as_l == sb + 3 * STAGE) as_l = sb;
    }

    float* ss = (float*)smem;          // [0..63]=sum, [64..127]=sumsq (local cols)
    if (do_stats) {
        if (tid < 128) ss[tid] = 0.f;
        __syncthreads();
    }

    // epilogue: /8192 + bias + prelu (+ deterministic column stats)
    float al = alpha[0];
    const float s = 1.f / 8192.f;
    float* dst = to_out ? outp : g_H;
    float ls[4][2] = {{0,0},{0,0},{0,0},{0,0}};
    float lq[4][2] = {{0,0},{0,0},{0,0},{0,0}};
#pragma unroll
    for (int ti = 0; ti < 2; ti++) {
        int row = m0 + wm * 32 + ti * 16 + (l >> 2);
#pragma unroll
        for (int tj = 0; tj < 4; tj++) {
            int col = n0 + wn * 32 + tj * 8 + (l & 3) * 2;
            float2 bb = *(const float2*)(bias + col);
            float v0 = acc[ti][tj][0] * s + bb.x;
            float v1 = acc[ti][tj][1] * s + bb.y;
            float v2 = acc[ti][tj][2] * s + bb.x;
            float v3 = acc[ti][tj][3] * s + bb.y;
            v0 = v0 >= 0.f ? v0 : al * v0;
            v1 = v1 >= 0.f ? v1 : al * v1;
            v2 = v2 >= 0.f ? v2 : al * v2;
            v3 = v3 >= 0.f ? v3 : al * v3;
            *(float2*)(dst + (size_t)row * 128 + col)       = make_float2(v0, v1);
            *(float2*)(dst + (size_t)(row + 8) * 128 + col) = make_float2(v2, v3);
            ls[tj][0] += v0 + v2;  lq[tj][0] += v0 * v0 + v2 * v2;
            ls[tj][1] += v1 + v3;  lq[tj][1] += v1 * v1 + v3 * v3;
        }
    }
    if (do_stats) {
        // reduce over the 8 lanes sharing (l&3): xor strides 4, 8, 16
#pragma unroll
        for (int d = 4; d < 32; d <<= 1) {
#pragma unroll
            for (int tj = 0; tj < 4; tj++)
#pragma unroll
                for (int p = 0; p < 2; p++) {
                    ls[tj][p] += __shfl_xor_sync(0xFFFFFFFFu, ls[tj][p], d);
                    lq[tj][p] += __shfl_xor_sync(0xFFFFFFFFu, lq[tj][p], d);
                }
        }
        if (l < 4) {
            // exactly 2 contributors per column (wm=0,1): commutative -> deterministic
#pragma unroll
            for (int tj = 0; tj < 4; tj++)
#pragma unroll
                for (int p = 0; p < 2; p++) {
                    int lc = wn * 32 + tj * 8 + l * 2 + p;
                    atomicAdd(&ss[lc],      ls[tj][p]);
                    atomicAdd(&ss[64 + lc], lq[tj][p]);
                }
        }
        __syncthreads();
        if (tid < 128) g_part[bx][tid] = ss[tid];
    }
}

// ---------------- launch ----------------
extern "C" void kernel_launch(void* const* d_in, const int* in_sizes, int n_in,
                              void* d_out, int out_size) {
    const float* x     = (const float*)d_in[0];
    const float* adj   = (const float*)d_in[1];
    const float* mask  = (const float*)d_in[2];
    const float* noise = (const float*)d_in[3];
    const float* eW = (const float*)d_in[4];
    const float* eb = (const float*)d_in[5];
    const float* ea = (const float*)d_in[6];
    const float* eg = (const float*)d_in[7];
    const float* eB = (const float*)d_in[8];
    const float* dW = (const float*)d_in[9];
    const float* db = (const float*)d_in[10];
    const float* da = (const float*)d_in[11];
    const float* dg = (const float*)d_in[12];
    const float* dB = (const float*)d_in[13];
    float* out = (float*)d_out;

    const int SMEM_BIG = 3 * 32768;                   // 98304
    const int SMEM_HW  = (64 * 129 + 128 * 128) * 4;  // 98560
    cudaFuncSetAttribute(k_big, cudaFuncAttributeMaxDynamicSharedMemorySize, SMEM_BIG);
    cudaFuncSetAttribute(k_hw,  cudaFuncAttributeMaxDynamicSharedMemorySize, SMEM_HW);

    k_convert<<<32768, 256>>>(adj);
    k_mask<<<1024, 256>>>(x, mask, noise, out);

    // 10 layers: j=0..4 encoder, j=5..9 decoder.
    // k_stats(j): BN params of layer j-1 -> g_bn.  k_hw(j): BN inline + @W_j -> g_B16.
    // k_big(j): adj@B + bias -> prelu -> g_H (or out for j=9), writes g_part.
    for (int j = 0; j < 10; j++) {
        const float *W, *bi, *al;
        if (j < 5) { W = eW + (size_t)j * 16384; bi = eb + j * 128; al = ea + j; }
        else { int i = j - 5; W = dW + (size_t)i * 16384; bi = db + i * 128; al = da + i; }

        if (j >= 1) {
            const float *g, *bt;
            if (j <= 5) { g = eg + (j - 1) * 128; bt = eB + (j - 1) * 128; }
            else        { g = dg + (j - 6) * 128; bt = dB + (j - 6) * 128; }
            k_stats<<<128, 128>>>(g, bt);
        }

        float* wout = (j == 5) ? out + (size_t)SEC : nullptr;  // encoded = BN(enc5 out)
        k_hw<<<128, 256, SMEM_HW>>>(W, j > 0 ? 1 : 0, wout);

        float* dst = (j == 9) ? out + 2 * (size_t)SEC : nullptr;
        k_big<<<256, 128, SMEM_BIG>>>(bi, al, dst, j == 9 ? 1 : 0, j < 9 ? 1 : 0);
    }
}